// round 2
// baseline (speedup 1.0000x reference)
#include <cuda_runtime.h>
#include <cstddef>

// Problem constants
#define BB    4
#define DD    32
#define WIN   14
#define HHH   17
#define KK    3
#define OO    32
#define HHALF 4
#define WW    12          // (14-3)/1+1
#define ROWS  (WW*WW)     // 144 sites per (b,d,ka,kb,o)
#define ROWF  17          // floats per output row
#define SLABF (ROWS*ROWF) // 2448 floats per block slab (16B-aligned chunks: 612 float4)
#define NTHR  256

__global__ void __launch_bounds__(NTHR)
convmat_kernel(const float* __restrict__ x,
               const float* __restrict__ wgt,
               float* __restrict__ out)
{
    __shared__ __align__(16) float sm[SLABF];
    __shared__ float wsm[16];

    const int bid = blockIdx.x;
    // decode (b, d, ka, kb, o) ; o fastest
    const int o    = bid & 31;
    int rest       = bid >> 5;
    const int kb   = rest % 3; rest /= 3;
    const int ka   = rest % 3; rest /= 3;
    const int d    = rest & 31;
    const int b    = rest >> 5;

    const int tid = threadIdx.x;

    // weight[d,ka,kb,o,p,m] : 16 contiguous floats
    if (tid < 16) {
        wsm[tid] = wgt[(size_t)((((d * KK + ka) * KK + kb) * OO + o) * 16) + tid];
    }
    __syncthreads();

    if (tid < ROWS) {
        const int wa = tid / WW;
        const int wb = tid - wa * WW;
        const int r  = wb + ka;   // x row = a1 + ka  (crossed indexing per reference)
        const int c  = wa + kb;   // x col = a0 + kb

        const float* xp = x + ((((size_t)(b * DD + d) * WIN) + r) * WIN + c) * HHH;

        float xv[17];
        #pragma unroll
        for (int i = 0; i < 17; ++i) xv[i] = xp[i];

        float* op = sm + tid * ROWF;
        #pragma unroll
        for (int p = 0; p < 4; ++p) {
            const float w0 = wsm[p * 4 + 0];
            const float w1 = wsm[p * 4 + 1];
            const float w2 = wsm[p * 4 + 2];
            const float w3 = wsm[p * 4 + 3];
            #pragma unroll
            for (int q = 0; q < 4; ++q) {
                float acc = w0 * xv[0 * 4 + q];
                acc = fmaf(w1, xv[1 * 4 + q], acc);
                acc = fmaf(w2, xv[2 * 4 + q], acc);
                acc = fmaf(w3, xv[3 * 4 + q], acc);
                op[p * 4 + q] = acc;
            }
        }
        op[16] = xv[16];   // activation passthrough
    }
    __syncthreads();

    // Stream slab to global as coalesced float4 stores.
    const float4* s4 = (const float4*)sm;
    float4* o4 = (float4*)(out + (size_t)bid * SLABF);
    #pragma unroll 1
    for (int i = tid; i < SLABF / 4; i += NTHR) {
        o4[i] = s4[i];
    }
}

extern "C" void kernel_launch(void* const* d_in, const int* in_sizes, int n_in,
                              void* d_out, int out_size)
{
    const float* x   = (const float*)d_in[0];
    const float* wgt = (const float*)d_in[1];
    float* out = (float*)d_out;

    const int grid = BB * DD * KK * KK * OO; // 36864
    convmat_kernel<<<grid, NTHR>>>(x, wgt, out);
}

// round 5
// speedup vs baseline: 1.8062x; 1.8062x over previous
#include <cuda_runtime.h>
#include <cstddef>

// Shapes
#define BB    4
#define DD    32
#define WIN   14
#define HHH   17
#define KK    3
#define OO    32
#define WW    12
#define ROWS  (WW*WW)       // 144 sites
#define ROWF  17
#define SLABF (ROWS*ROWF)   // 2448 floats per (b,d,ka,kb,o)
#define XTILE (WIN*WIN*HHH) // 3332 floats per (b,d) slice (13328 B, /4 = 833 float4)
#define WBLK  (OO*16)       // 512 weight floats per (d,ka,kb)
#define NTHR  160

__global__ void __launch_bounds__(NTHR, 8)
convmat_kernel(const float* __restrict__ x,
               const float* __restrict__ wgt,
               float* __restrict__ out)
{
    __shared__ __align__(16) float xs[XTILE];   // 13328 B
    __shared__ __align__(16) float wsm[WBLK];   //  2048 B
    __shared__ __align__(16) float rsm[SLABF];  //  9792 B

    const int bid = blockIdx.x;          // (b, d, ka, kb), kb fastest
    const int kb  = bid % 3;
    const int ka  = (bid / 3) % 3;
    const int d   = (bid / 9) & 31;
    const int b   = bid / 288;

    const int tid = threadIdx.x;

    // Coalesced load of the full (b,d) x slice into shared (float4).
    {
        const float4* xg = (const float4*)(x + (size_t)(b * DD + d) * XTILE);
        float4* xs4 = (float4*)xs;
        #pragma unroll 2
        for (int i = tid; i < XTILE / 4; i += NTHR) xs4[i] = xg[i];
    }
    // All 32 o-weights for this (d,ka,kb): 512 contiguous floats.
    {
        const float4* wg = (const float4*)(wgt + (size_t)((d * KK + ka) * KK + kb) * WBLK);
        float4* ws4 = (float4*)wsm;
        if (tid < WBLK / 4) ws4[tid] = wg[tid];
    }
    __syncthreads();

    // Per-site x row cached in registers (conflict-free LDS: stride 17, odd).
    float xv[17];
    if (tid < ROWS) {
        const int wa = tid / WW;
        const int wb = tid - wa * WW;
        const int r  = wb + ka;              // crossed indexing per reference
        const int c  = wa + kb;
        const float* xp = xs + (r * WIN + c) * HHH;
        #pragma unroll
        for (int i = 0; i < 17; ++i) xv[i] = xp[i];
        rsm[tid * ROWF + 16] = xv[16];       // activation passthrough, constant over o
    }

    float* const outb = out + (size_t)bid * (OO * SLABF);

    for (int o = 0; o < OO; ++o) {
        if (tid < ROWS) {
            const float* w = wsm + o * 16;   // broadcast loads (same addr all lanes)
            float* op = rsm + tid * ROWF;
            #pragma unroll
            for (int p = 0; p < 4; ++p) {
                const float w0 = w[p * 4 + 0];
                const float w1 = w[p * 4 + 1];
                const float w2 = w[p * 4 + 2];
                const float w3 = w[p * 4 + 3];
                #pragma unroll
                for (int q = 0; q < 4; ++q) {
                    float acc = w0 * xv[q];
                    acc = fmaf(w1, xv[4 + q], acc);
                    acc = fmaf(w2, xv[8 + q], acc);
                    acc = fmaf(w3, xv[12 + q], acc);
                    op[p * 4 + q] = acc;
                }
            }
        }
        __syncthreads();

        // Coalesced float4 dump of the 9792 B slab.
        const float4* r4 = (const float4*)rsm;
        float4* o4 = (float4*)(outb + (size_t)o * SLABF);
        #pragma unroll 1
        for (int i = tid; i < SLABF / 4; i += NTHR) o4[i] = r4[i];
        __syncthreads();   // dump must finish before next o overwrites rsm
    }
}

extern "C" void kernel_launch(void* const* d_in, const int* in_sizes, int n_in,
                              void* d_out, int out_size)
{
    const float* x   = (const float*)d_in[0];
    const float* wgt = (const float*)d_in[1];
    float* out = (float*)d_out;

    const int grid = BB * DD * KK * KK;  // 1152 blocks, one per (b,d,ka,kb)
    convmat_kernel<<<grid, NTHR>>>(x, wgt, out);
}